// round 1
// baseline (speedup 1.0000x reference)
#include <cuda_runtime.h>
#include <cuda_bf16.h>
#include <cstdint>

// Problem constants
#define BATCH 64
#define SEQ   512
#define DIN   512
#define MEM   256
#define HID   512

// ---------------- scratch (device globals; no allocs allowed) ----------------
__device__ float g_u[BATCH * SEQ];                 // 128 KB
__device__ float g_H[MEM * SEQ];                   // H[k][d], 512 KB
__device__ float g_P[2][MEM * MEM];                // ping-pong A^len, 512 KB
__device__ float g_m[(size_t)BATCH * SEQ * MEM];   // 33.5 MB

// ---------------- kernel 0: init H col0 = B, P0 = A ----------------
__global__ void k_init(const float* __restrict__ A, const float* __restrict__ B) {
    int i = blockIdx.x * 256 + threadIdx.x;     // grid 256 x 256 = 65536
    g_P[0][i] = A[i];
    if (i < MEM) g_H[i * SEQ] = B[i];
}

// ---------------- kernel 1: u[b,t] = relu(x[b,t,:] . Wu_w + b0) ----------------
__global__ void k_u(const float* __restrict__ x, const float* __restrict__ w,
                    const float* __restrict__ bptr, float* __restrict__ u) {
    __shared__ __align__(16) float ws[DIN];
    int tid = threadIdx.x;                      // 256 threads
    ws[tid] = w[tid];
    ws[tid + 256] = w[tid + 256];
    __syncthreads();
    int warp = tid >> 5, lane = tid & 31;
    int row = blockIdx.x * 8 + warp;            // grid 4096 -> 32768 rows
    const float4* x4 = (const float4*)(x + (size_t)row * DIN);
    const float4* w4 = (const float4*)ws;
    float s = 0.f;
#pragma unroll
    for (int i = lane; i < DIN / 4; i += 32) {
        float4 xv = x4[i];
        float4 wv = w4[i];
        s += xv.x * wv.x + xv.y * wv.y + xv.z * wv.z + xv.w * wv.w;
    }
#pragma unroll
    for (int o = 16; o > 0; o >>= 1) s += __shfl_xor_sync(0xffffffffu, s, o);
    if (lane == 0) u[row] = fmaxf(s + bptr[0], 0.f);
}

// ---------------- kernel 2: small GEMM C = P(256x256) @ S(256xN) ----------------
// C[i*ldC + c] = sum_j P[i*256+j] * S[j*ldS + c]
__global__ void k_gemm256(const float* __restrict__ P, const float* __restrict__ S,
                          int ldS, float* __restrict__ C, int ldC, int N) {
    __shared__ float Ps[32][33];
    __shared__ float Ss[32][33];
    int tx = threadIdx.x & 15, ty = threadIdx.x >> 4;   // 16x16
    int i0 = blockIdx.y * 32;
    int c0 = blockIdx.x * 32;
    float acc00 = 0, acc01 = 0, acc10 = 0, acc11 = 0;
    for (int k0 = 0; k0 < 256; k0 += 32) {
#pragma unroll
        for (int l = 0; l < 4; l++) {
            int idx = threadIdx.x + l * 256;
            int r = idx >> 5, cc = idx & 31;
            Ps[r][cc] = P[(i0 + r) * 256 + k0 + cc];
            int c = c0 + cc;
            Ss[r][cc] = (c < N) ? S[(size_t)(k0 + r) * ldS + c] : 0.f;
        }
        __syncthreads();
#pragma unroll
        for (int k = 0; k < 32; k++) {
            float a0 = Ps[ty * 2][k], a1 = Ps[ty * 2 + 1][k];
            float b0 = Ss[k][tx * 2], b1 = Ss[k][tx * 2 + 1];
            acc00 += a0 * b0; acc01 += a0 * b1;
            acc10 += a1 * b0; acc11 += a1 * b1;
        }
        __syncthreads();
    }
    int i = i0 + ty * 2, c = c0 + tx * 2;
    if (c < N)     { C[(size_t)i * ldC + c] = acc00; C[(size_t)(i + 1) * ldC + c] = acc10; }
    if (c + 1 < N) { C[(size_t)i * ldC + c + 1] = acc01; C[(size_t)(i + 1) * ldC + c + 1] = acc11; }
}

// ---------------- kernel 3: causal conv m[b,t,k] = sum_d H[k,d] u[b,t-d] ----------------
// grid (4 ktiles, 8 ttiles, 64 batch), 256 threads, 64x64 output tile, 4x4 micro
__global__ __launch_bounds__(256) void k_conv(const float* __restrict__ u,
                                              float* __restrict__ mm) {
    __shared__ __align__(16) float Hs[64][68];  // Hs[dd][kk]
    __shared__ float us[128];
    int b = blockIdx.z;
    int t0 = blockIdx.y * 64;
    int k0 = blockIdx.x * 64;
    int tid = threadIdx.x;
    int tx = tid & 15, ty = tid >> 4;
    const float* urow = u + b * SEQ;
    float acc[4][4] = {};
    int ndc = blockIdx.y + 1;                   // causal: skip chunks with d > t
    for (int dc = 0; dc < ndc; dc++) {
        int d0 = dc * 64;
        if (tid < 128) {
            int idx = t0 - d0 - 63 + tid;
            us[tid] = (idx >= 0 && idx < SEQ) ? urow[idx] : 0.f;
        }
#pragma unroll
        for (int l = 0; l < 16; l++) {
            int idx = tid + l * 256;
            int dd = idx & 63, kk = idx >> 6;
            Hs[dd][kk] = g_H[(size_t)(k0 + kk) * SEQ + d0 + dd];
        }
        __syncthreads();
#pragma unroll
        for (int dd = 0; dd < 64; dd++) {
            float4 hv = *(const float4*)&Hs[dd][tx * 4];
            float uv[4];
#pragma unroll
            for (int q = 0; q < 4; q++) uv[q] = us[ty * 4 + q + 63 - dd];
#pragma unroll
            for (int q = 0; q < 4; q++) {
                acc[q][0] += uv[q] * hv.x;
                acc[q][1] += uv[q] * hv.y;
                acc[q][2] += uv[q] * hv.z;
                acc[q][3] += uv[q] * hv.w;
            }
        }
        __syncthreads();
    }
#pragma unroll
    for (int q = 0; q < 4; q++) {
        int t = t0 + ty * 4 + q;
        float4 v = make_float4(acc[q][0], acc[q][1], acc[q][2], acc[q][3]);
        *(float4*)&mm[((size_t)b * SEQ + t) * MEM + k0 + tx * 4] = v;
    }
}

// ---------------- kernel 4: h = relu([m|x] @ Wh + b), h_n = h[:,511,:] ----------------
// 32768x512, K=768. BM=BN=128, BK=8, 256 threads, 8x8 micro, double-buffered smem.
__global__ __launch_bounds__(256) void k_h(const float* __restrict__ mm,
                                           const float* __restrict__ x,
                                           const float* __restrict__ W,
                                           const float* __restrict__ bias,
                                           float* __restrict__ h,
                                           float* __restrict__ hn) {
    __shared__ __align__(16) float As[2][8][132];
    __shared__ __align__(16) float Bs[2][8][128];
    int tid = threadIdx.x;
    int tx = tid & 15, ty = tid >> 4;
    int n0 = blockIdx.x * 128;
    int m0 = blockIdx.y * 128;
    int ar = tid >> 1, ako = (tid & 1) * 4;     // A tile: 128 rows x 8k
    int br = tid >> 5, bn = (tid & 31) * 4;     // B tile: 8k x 128 n

    float acc[8][8] = {};
    float4 pa, pb;

    // prologue: tile kt=0
    {
        int row = m0 + ar;
        pa = *(const float4*)(mm + (size_t)row * MEM + ako);  // kt=0 < 256 -> m region
        pb = *(const float4*)(W + (size_t)br * HID + n0 + bn);
    }
    int buf = 0;
    As[0][ako + 0][ar] = pa.x; As[0][ako + 1][ar] = pa.y;
    As[0][ako + 2][ar] = pa.z; As[0][ako + 3][ar] = pa.w;
    *(float4*)&Bs[0][br][bn] = pb;
    __syncthreads();

    for (int kt = 0; kt < MEM + DIN; kt += 8) {
        int nkt = kt + 8;
        if (nkt < MEM + DIN) {
            int row = m0 + ar;
            int k = nkt + ako;
            const float* p = (k < MEM) ? (mm + (size_t)row * MEM + k)
                                       : (x + (size_t)row * DIN + (k - MEM));
            pa = *(const float4*)p;
            pb = *(const float4*)(W + (size_t)(nkt + br) * HID + n0 + bn);
        }
#pragma unroll
        for (int k = 0; k < 8; k++) {
            float a[8], bb[8];
            *(float4*)&a[0] = *(const float4*)&As[buf][k][ty * 8];
            *(float4*)&a[4] = *(const float4*)&As[buf][k][ty * 8 + 4];
            *(float4*)&bb[0] = *(const float4*)&Bs[buf][k][tx * 8];
            *(float4*)&bb[4] = *(const float4*)&Bs[buf][k][tx * 8 + 4];
#pragma unroll
            for (int i = 0; i < 8; i++)
#pragma unroll
                for (int j = 0; j < 8; j++)
                    acc[i][j] += a[i] * bb[j];
        }
        if (nkt < MEM + DIN) {
            buf ^= 1;
            As[buf][ako + 0][ar] = pa.x; As[buf][ako + 1][ar] = pa.y;
            As[buf][ako + 2][ar] = pa.z; As[buf][ako + 3][ar] = pa.w;
            *(float4*)&Bs[buf][br][bn] = pb;
            __syncthreads();
        }
    }

    float bv[8];
    *(float4*)&bv[0] = *(const float4*)(bias + n0 + tx * 8);
    *(float4*)&bv[4] = *(const float4*)(bias + n0 + tx * 8 + 4);
#pragma unroll
    for (int i = 0; i < 8; i++) {
        int row = m0 + ty * 8 + i;
        float4 v0, v1;
        v0.x = fmaxf(acc[i][0] + bv[0], 0.f);
        v0.y = fmaxf(acc[i][1] + bv[1], 0.f);
        v0.z = fmaxf(acc[i][2] + bv[2], 0.f);
        v0.w = fmaxf(acc[i][3] + bv[3], 0.f);
        v1.x = fmaxf(acc[i][4] + bv[4], 0.f);
        v1.y = fmaxf(acc[i][5] + bv[5], 0.f);
        v1.z = fmaxf(acc[i][6] + bv[6], 0.f);
        v1.w = fmaxf(acc[i][7] + bv[7], 0.f);
        *(float4*)&h[(size_t)row * HID + n0 + tx * 8] = v0;
        *(float4*)&h[(size_t)row * HID + n0 + tx * 8 + 4] = v1;
        if ((row & (SEQ - 1)) == SEQ - 1) {
            int bidx = row >> 9;
            *(float4*)&hn[(size_t)bidx * HID + n0 + tx * 8] = v0;
            *(float4*)&hn[(size_t)bidx * HID + n0 + tx * 8 + 4] = v1;
        }
    }
}

// ---------------- launch ----------------
extern "C" void kernel_launch(void* const* d_in, const int* in_sizes, int n_in,
                              void* d_out, int out_size) {
    const float* x    = (const float*)d_in[0];   // (64,512,512)
    const float* Wu_w = (const float*)d_in[1];   // (512,1)
    const float* Wu_b = (const float*)d_in[2];   // (1,)
    const float* Wh_w = (const float*)d_in[3];   // (768,512)
    const float* Wh_b = (const float*)d_in[4];   // (512,)
    const float* A    = (const float*)d_in[5];   // (256,256)
    const float* B    = (const float*)d_in[6];   // (256,1)

    float* out = (float*)d_out;
    float* h  = out;                                  // (64,512,512)
    float* hn = out + (size_t)BATCH * SEQ * HID;      // (64,512)

    float *pU, *pH, *pM, *pPbase;
    cudaGetSymbolAddress((void**)&pU, g_u);
    cudaGetSymbolAddress((void**)&pH, g_H);
    cudaGetSymbolAddress((void**)&pM, g_m);
    cudaGetSymbolAddress((void**)&pPbase, g_P);
    float* pP[2] = { pPbase, pPbase + MEM * MEM };

    // init P=A, H[:,0]=B
    k_init<<<256, 256>>>(A, B);

    // u projection
    k_u<<<BATCH * SEQ / 8, 256>>>(x, Wu_w, Wu_b, pU);

    // H via doubling: H[:, len:2len] = P @ H[:, 0:len];  P <- P@P
    int cur = 0;
    for (int len = 1; len <= 256; len <<= 1) {
        dim3 g1((len + 31) / 32, 8);
        k_gemm256<<<g1, 256>>>(pP[cur], pH, SEQ, pH + len, SEQ, len);
        if (len < 256) {
            k_gemm256<<<dim3(8, 8), 256>>>(pP[cur], pP[cur], MEM, pP[cur ^ 1], MEM, MEM);
            cur ^= 1;
        }
    }

    // causal convolution
    k_conv<<<dim3(MEM / 64, SEQ / 64, BATCH), 256>>>(pU, pM);

    // fused output GEMM + bias + relu + h_n
    k_h<<<dim3(HID / 128, BATCH * SEQ / 128), 256>>>(pM, x, Wh_w, Wh_b, h, hn);
}

// round 2
// speedup vs baseline: 1.0043x; 1.0043x over previous
#include <cuda_runtime.h>
#include <cuda_bf16.h>
#include <cstdint>

// Problem constants
#define BATCH 64
#define SEQ   512
#define DIN   512
#define MEM   256
#define HID   512

// ---------------- scratch (device globals; no allocs allowed) ----------------
__device__ float g_u[BATCH * SEQ];                 // 128 KB
__device__ float g_H[MEM * SEQ];                   // H[k][d], 512 KB
__device__ float g_P[2][MEM * MEM];                // ping-pong A^len, 512 KB
__device__ float g_m[(size_t)BATCH * SEQ * MEM];   // 33.5 MB

// ---------------- kernel 0: init H col0 = B, P0 = A ----------------
__global__ void k_init(const float* __restrict__ A, const float* __restrict__ B) {
    int i = blockIdx.x * 256 + threadIdx.x;     // grid 256 x 256 = 65536
    g_P[0][i] = A[i];
    if (i < MEM) g_H[i * SEQ] = B[i];
}

// ---------------- kernel 1: u[b,t] = relu(x[b,t,:] . Wu_w + b0) ----------------
__global__ void k_u(const float* __restrict__ x, const float* __restrict__ w,
                    const float* __restrict__ bptr, float* __restrict__ u) {
    __shared__ __align__(16) float ws[DIN];
    int tid = threadIdx.x;                      // 256 threads
    ws[tid] = w[tid];
    ws[tid + 256] = w[tid + 256];
    __syncthreads();
    int warp = tid >> 5, lane = tid & 31;
    int row = blockIdx.x * 8 + warp;            // grid 4096 -> 32768 rows
    const float4* x4 = (const float4*)(x + (size_t)row * DIN);
    const float4* w4 = (const float4*)ws;
    float s = 0.f;
#pragma unroll
    for (int i = lane; i < DIN / 4; i += 32) {
        float4 xv = x4[i];
        float4 wv = w4[i];
        s += xv.x * wv.x + xv.y * wv.y + xv.z * wv.z + xv.w * wv.w;
    }
#pragma unroll
    for (int o = 16; o > 0; o >>= 1) s += __shfl_xor_sync(0xffffffffu, s, o);
    if (lane == 0) u[row] = fmaxf(s + bptr[0], 0.f);
}

// ---------------- kernel 2: small GEMM C = P(256x256) @ S(256xN) ----------------
// C[i*ldC + c] = sum_j P[i*256+j] * S[j*ldS + c]
__global__ void k_gemm256(const float* __restrict__ P, const float* __restrict__ S,
                          int ldS, float* __restrict__ C, int ldC, int N) {
    __shared__ float Ps[32][33];
    __shared__ float Ss[32][33];
    int tx = threadIdx.x & 15, ty = threadIdx.x >> 4;   // 16x16
    int i0 = blockIdx.y * 32;
    int c0 = blockIdx.x * 32;
    float acc00 = 0, acc01 = 0, acc10 = 0, acc11 = 0;
    for (int k0 = 0; k0 < 256; k0 += 32) {
#pragma unroll
        for (int l = 0; l < 4; l++) {
            int idx = threadIdx.x + l * 256;
            int r = idx >> 5, cc = idx & 31;
            Ps[r][cc] = P[(i0 + r) * 256 + k0 + cc];
            int c = c0 + cc;
            Ss[r][cc] = (c < N) ? S[(size_t)(k0 + r) * ldS + c] : 0.f;
        }
        __syncthreads();
#pragma unroll
        for (int k = 0; k < 32; k++) {
            float a0 = Ps[ty * 2][k], a1 = Ps[ty * 2 + 1][k];
            float b0 = Ss[k][tx * 2], b1 = Ss[k][tx * 2 + 1];
            acc00 += a0 * b0; acc01 += a0 * b1;
            acc10 += a1 * b0; acc11 += a1 * b1;
        }
        __syncthreads();
    }
    int i = i0 + ty * 2, c = c0 + tx * 2;
    if (c < N)     { C[(size_t)i * ldC + c] = acc00; C[(size_t)(i + 1) * ldC + c] = acc10; }
    if (c + 1 < N) { C[(size_t)i * ldC + c + 1] = acc01; C[(size_t)(i + 1) * ldC + c + 1] = acc11; }
}

// ---------------- kernel 3: causal conv m[b,t,k] = sum_d H[k,d] u[b,t-d] ----------------
// grid (4 ktiles, 8 ttiles, 64 batch), 256 threads, 64x64 output tile, 4x4 micro
__global__ __launch_bounds__(256) void k_conv(const float* __restrict__ u,
                                              float* __restrict__ mm) {
    __shared__ __align__(16) float Hs[64][68];  // Hs[dd][kk]
    __shared__ float us[128];
    int b = blockIdx.z;
    int t0 = blockIdx.y * 64;
    int k0 = blockIdx.x * 64;
    int tid = threadIdx.x;
    int tx = tid & 15, ty = tid >> 4;
    const float* urow = u + b * SEQ;
    float acc[4][4] = {};
    int ndc = blockIdx.y + 1;                   // causal: skip chunks with d > t
    for (int dc = 0; dc < ndc; dc++) {
        int d0 = dc * 64;
        if (tid < 128) {
            int idx = t0 - d0 - 63 + tid;
            us[tid] = (idx >= 0 && idx < SEQ) ? urow[idx] : 0.f;
        }
#pragma unroll
        for (int l = 0; l < 16; l++) {
            int idx = tid + l * 256;
            int dd = idx & 63, kk = idx >> 6;
            Hs[dd][kk] = g_H[(size_t)(k0 + kk) * SEQ + d0 + dd];
        }
        __syncthreads();
#pragma unroll
        for (int dd = 0; dd < 64; dd++) {
            float4 hv = *(const float4*)&Hs[dd][tx * 4];
            float uv[4];
#pragma unroll
            for (int q = 0; q < 4; q++) uv[q] = us[ty * 4 + q + 63 - dd];
#pragma unroll
            for (int q = 0; q < 4; q++) {
                acc[q][0] += uv[q] * hv.x;
                acc[q][1] += uv[q] * hv.y;
                acc[q][2] += uv[q] * hv.z;
                acc[q][3] += uv[q] * hv.w;
            }
        }
        __syncthreads();
    }
#pragma unroll
    for (int q = 0; q < 4; q++) {
        int t = t0 + ty * 4 + q;
        float4 v = make_float4(acc[q][0], acc[q][1], acc[q][2], acc[q][3]);
        *(float4*)&mm[((size_t)b * SEQ + t) * MEM + k0 + tx * 4] = v;
    }
}

// ---------------- kernel 4: h = relu([m|x] @ Wh + b), h_n = h[:,511,:] ----------------
// 32768x512, K=768. BM=BN=128, BK=8, 256 threads, 8x8 micro, double-buffered smem.
__global__ __launch_bounds__(256) void k_h(const float* __restrict__ mm,
                                           const float* __restrict__ x,
                                           const float* __restrict__ W,
                                           const float* __restrict__ bias,
                                           float* __restrict__ h,
                                           float* __restrict__ hn) {
    __shared__ __align__(16) float As[2][8][132];
    __shared__ __align__(16) float Bs[2][8][128];
    int tid = threadIdx.x;
    int tx = tid & 15, ty = tid >> 4;
    int n0 = blockIdx.x * 128;
    int m0 = blockIdx.y * 128;
    int ar = tid >> 1, ako = (tid & 1) * 4;     // A tile: 128 rows x 8k
    int br = tid >> 5, bn = (tid & 31) * 4;     // B tile: 8k x 128 n

    float acc[8][8] = {};
    float4 pa, pb;

    // prologue: tile kt=0
    {
        int row = m0 + ar;
        pa = *(const float4*)(mm + (size_t)row * MEM + ako);  // kt=0 < 256 -> m region
        pb = *(const float4*)(W + (size_t)br * HID + n0 + bn);
    }
    int buf = 0;
    As[0][ako + 0][ar] = pa.x; As[0][ako + 1][ar] = pa.y;
    As[0][ako + 2][ar] = pa.z; As[0][ako + 3][ar] = pa.w;
    *(float4*)&Bs[0][br][bn] = pb;
    __syncthreads();

    for (int kt = 0; kt < MEM + DIN; kt += 8) {
        int nkt = kt + 8;
        if (nkt < MEM + DIN) {
            int row = m0 + ar;
            int k = nkt + ako;
            const float* p = (k < MEM) ? (mm + (size_t)row * MEM + k)
                                       : (x + (size_t)row * DIN + (k - MEM));
            pa = *(const float4*)p;
            pb = *(const float4*)(W + (size_t)(nkt + br) * HID + n0 + bn);
        }
#pragma unroll
        for (int k = 0; k < 8; k++) {
            float a[8], bb[8];
            *(float4*)&a[0] = *(const float4*)&As[buf][k][ty * 8];
            *(float4*)&a[4] = *(const float4*)&As[buf][k][ty * 8 + 4];
            *(float4*)&bb[0] = *(const float4*)&Bs[buf][k][tx * 8];
            *(float4*)&bb[4] = *(const float4*)&Bs[buf][k][tx * 8 + 4];
#pragma unroll
            for (int i = 0; i < 8; i++)
#pragma unroll
                for (int j = 0; j < 8; j++)
                    acc[i][j] += a[i] * bb[j];
        }
        if (nkt < MEM + DIN) {
            buf ^= 1;
            As[buf][ako + 0][ar] = pa.x; As[buf][ako + 1][ar] = pa.y;
            As[buf][ako + 2][ar] = pa.z; As[buf][ako + 3][ar] = pa.w;
            *(float4*)&Bs[buf][br][bn] = pb;
            __syncthreads();
        }
    }

    float bv[8];
    *(float4*)&bv[0] = *(const float4*)(bias + n0 + tx * 8);
    *(float4*)&bv[4] = *(const float4*)(bias + n0 + tx * 8 + 4);
#pragma unroll
    for (int i = 0; i < 8; i++) {
        int row = m0 + ty * 8 + i;
        float4 v0, v1;
        v0.x = fmaxf(acc[i][0] + bv[0], 0.f);
        v0.y = fmaxf(acc[i][1] + bv[1], 0.f);
        v0.z = fmaxf(acc[i][2] + bv[2], 0.f);
        v0.w = fmaxf(acc[i][3] + bv[3], 0.f);
        v1.x = fmaxf(acc[i][4] + bv[4], 0.f);
        v1.y = fmaxf(acc[i][5] + bv[5], 0.f);
        v1.z = fmaxf(acc[i][6] + bv[6], 0.f);
        v1.w = fmaxf(acc[i][7] + bv[7], 0.f);
        *(float4*)&h[(size_t)row * HID + n0 + tx * 8] = v0;
        *(float4*)&h[(size_t)row * HID + n0 + tx * 8 + 4] = v1;
        if ((row & (SEQ - 1)) == SEQ - 1) {
            int bidx = row >> 9;
            *(float4*)&hn[(size_t)bidx * HID + n0 + tx * 8] = v0;
            *(float4*)&hn[(size_t)bidx * HID + n0 + tx * 8 + 4] = v1;
        }
    }
}

// ---------------- launch ----------------
extern "C" void kernel_launch(void* const* d_in, const int* in_sizes, int n_in,
                              void* d_out, int out_size) {
    const float* x    = (const float*)d_in[0];   // (64,512,512)
    const float* Wu_w = (const float*)d_in[1];   // (512,1)
    const float* Wu_b = (const float*)d_in[2];   // (1,)
    const float* Wh_w = (const float*)d_in[3];   // (768,512)
    const float* Wh_b = (const float*)d_in[4];   // (512,)
    const float* A    = (const float*)d_in[5];   // (256,256)
    const float* B    = (const float*)d_in[6];   // (256,1)

    float* out = (float*)d_out;
    float* h  = out;                                  // (64,512,512)
    float* hn = out + (size_t)BATCH * SEQ * HID;      // (64,512)

    float *pU, *pH, *pM, *pPbase;
    cudaGetSymbolAddress((void**)&pU, g_u);
    cudaGetSymbolAddress((void**)&pH, g_H);
    cudaGetSymbolAddress((void**)&pM, g_m);
    cudaGetSymbolAddress((void**)&pPbase, g_P);
    float* pP[2] = { pPbase, pPbase + MEM * MEM };

    // init P=A, H[:,0]=B
    k_init<<<256, 256>>>(A, B);

    // u projection
    k_u<<<BATCH * SEQ / 8, 256>>>(x, Wu_w, Wu_b, pU);

    // H via doubling: H[:, len:2len] = P @ H[:, 0:len];  P <- P@P
    int cur = 0;
    for (int len = 1; len <= 256; len <<= 1) {
        dim3 g1((len + 31) / 32, 8);
        k_gemm256<<<g1, 256>>>(pP[cur], pH, SEQ, pH + len, SEQ, len);
        if (len < 256) {
            k_gemm256<<<dim3(8, 8), 256>>>(pP[cur], pP[cur], MEM, pP[cur ^ 1], MEM, MEM);
            cur ^= 1;
        }
    }

    // causal convolution
    k_conv<<<dim3(MEM / 64, SEQ / 64, BATCH), 256>>>(pU, pM);

    // fused output GEMM + bias + relu + h_n
    k_h<<<dim3(HID / 128, BATCH * SEQ / 128), 256>>>(pM, x, Wh_w, Wh_b, h, hn);
}

// round 3
// speedup vs baseline: 2.2746x; 2.2648x over previous
#include <cuda_runtime.h>
#include <cuda_bf16.h>
#include <cstdint>

#define BATCH 64
#define SEQ   512
#define DIN   512
#define MEM   256
#define HID   512

// ---------------- scratch ----------------
__device__ float g_u[BATCH * SEQ];
__device__ float g_H[MEM * SEQ];
__device__ float g_P[2][MEM * MEM];
__device__ float g_m[(size_t)BATCH * SEQ * MEM];

// ---------------- helpers ----------------
__device__ __forceinline__ uint32_t f2tf(float x) {
    uint32_t r;
    asm("cvt.rna.tf32.f32 %0, %1;" : "=r"(r) : "f"(x));
    return r;
}
__device__ __forceinline__ void mma_tf32(float* d, const uint32_t* a,
                                         const uint32_t* b, const float* c) {
    asm volatile(
        "mma.sync.aligned.m16n8k8.row.col.f32.tf32.tf32.f32 "
        "{%0,%1,%2,%3}, {%4,%5,%6,%7}, {%8,%9}, {%10,%11,%12,%13};\n"
        : "=f"(d[0]), "=f"(d[1]), "=f"(d[2]), "=f"(d[3])
        : "r"(a[0]), "r"(a[1]), "r"(a[2]), "r"(a[3]),
          "r"(b[0]), "r"(b[1]),
          "f"(c[0]), "f"(c[1]), "f"(c[2]), "f"(c[3]));
}

// ---------------- kernel 0: init ----------------
__global__ void k_init(const float* __restrict__ A, const float* __restrict__ B) {
    int i = blockIdx.x * 256 + threadIdx.x;
    g_P[0][i] = A[i];
    if (i < MEM) g_H[i * SEQ] = B[i];
}

// ---------------- kernel 1: u projection ----------------
__global__ void k_u(const float* __restrict__ x, const float* __restrict__ w,
                    const float* __restrict__ bptr, float* __restrict__ u) {
    __shared__ __align__(16) float ws[DIN];
    int tid = threadIdx.x;
    ws[tid] = w[tid];
    ws[tid + 256] = w[tid + 256];
    __syncthreads();
    int warp = tid >> 5, lane = tid & 31;
    int row = blockIdx.x * 8 + warp;
    const float4* x4 = (const float4*)(x + (size_t)row * DIN);
    const float4* w4 = (const float4*)ws;
    float s = 0.f;
#pragma unroll
    for (int i = lane; i < DIN / 4; i += 32) {
        float4 xv = x4[i];
        float4 wv = w4[i];
        s += xv.x * wv.x + xv.y * wv.y + xv.z * wv.z + xv.w * wv.w;
    }
#pragma unroll
    for (int o = 16; o > 0; o >>= 1) s += __shfl_xor_sync(0xffffffffu, s, o);
    if (lane == 0) u[row] = fmaxf(s + bptr[0], 0.f);
}

// ---------------- kernel 2: fused doubling stage (fp32) ----------------
// z=0: H[:, len:2len] = P @ H[:, 0:len]   (ld 512)
// z=1: Pout = P @ P                        (ld 256, only if doP2)
__global__ void k_stage(const float* __restrict__ P, float* __restrict__ H,
                        int len, float* __restrict__ Pout, int doP2) {
    const float* S;
    float* C;
    int ldS, ldC, N;
    if (blockIdx.z == 0) {
        S = H; ldS = SEQ; C = H + len; ldC = SEQ; N = len;
    } else {
        if (!doP2) return;
        S = P; ldS = MEM; C = Pout; ldC = MEM; N = MEM;
    }
    int c0 = blockIdx.x * 32;
    if (c0 >= N) return;
    __shared__ float Ps[32][33];
    __shared__ float Ss[32][33];
    int tx = threadIdx.x & 15, ty = threadIdx.x >> 4;
    int i0 = blockIdx.y * 32;
    float acc00 = 0, acc01 = 0, acc10 = 0, acc11 = 0;
    for (int k0 = 0; k0 < 256; k0 += 32) {
#pragma unroll
        for (int l = 0; l < 4; l++) {
            int idx = threadIdx.x + l * 256;
            int r = idx >> 5, cc = idx & 31;
            Ps[r][cc] = P[(i0 + r) * 256 + k0 + cc];
            int c = c0 + cc;
            Ss[r][cc] = (c < N) ? S[(size_t)(k0 + r) * ldS + c] : 0.f;
        }
        __syncthreads();
#pragma unroll
        for (int k = 0; k < 32; k++) {
            float a0 = Ps[ty * 2][k], a1 = Ps[ty * 2 + 1][k];
            float b0 = Ss[k][tx * 2], b1 = Ss[k][tx * 2 + 1];
            acc00 += a0 * b0; acc01 += a0 * b1;
            acc10 += a1 * b0; acc11 += a1 * b1;
        }
        __syncthreads();
    }
    int i = i0 + ty * 2, c = c0 + tx * 2;
    if (c < N)     { C[(size_t)i * ldC + c] = acc00; C[(size_t)(i + 1) * ldC + c] = acc10; }
    if (c + 1 < N) { C[(size_t)i * ldC + c + 1] = acc01; C[(size_t)(i + 1) * ldC + c + 1] = acc11; }
}

// ---------------- kernel 3: causal conv, tf32 tensor cores ----------------
// m[b,t,k] = sum_d H[k,d] u[b,t-d].  Per block: 64(t) x 64(k) tile.
// A[t,d] = u[t-d] (row-major Toeplitz from smem), B[d,k] = H[k,d] (col-major frag).
__global__ __launch_bounds__(128) void k_conv(const float* __restrict__ u,
                                              float* __restrict__ mm) {
    __shared__ uint32_t us[128];
    __shared__ uint32_t Hs[64][68];
    int b = blockIdx.z;
    int t0 = blockIdx.y * 64;
    int k0 = blockIdx.x * 64;
    int tid = threadIdx.x;
    int lane = tid & 31, wid = tid >> 5;
    int wm = (wid & 1) * 32, wn = (wid >> 1) * 32;
    int lp = lane >> 2, lq = lane & 3;
    const float* urow = u + b * SEQ;

    float acc[2][4][4] = {};
    int ndc = blockIdx.y + 1;
    for (int dc = 0; dc < ndc; dc++) {
        int d0 = dc * 64;
        {
            int idx = t0 - d0 - 63 + tid;
            us[tid] = f2tf((idx >= 0 && idx < SEQ) ? urow[idx] : 0.f);
        }
        {
            int hr = tid >> 1;
            int hc0 = (tid & 1) * 32;
            const float4* hrow = (const float4*)(g_H + (size_t)(k0 + hr) * SEQ + d0 + hc0);
#pragma unroll
            for (int j = 0; j < 8; j++) {
                float4 v = hrow[j];
                Hs[hr][hc0 + j * 4 + 0] = f2tf(v.x);
                Hs[hr][hc0 + j * 4 + 1] = f2tf(v.y);
                Hs[hr][hc0 + j * 4 + 2] = f2tf(v.z);
                Hs[hr][hc0 + j * 4 + 3] = f2tf(v.w);
            }
        }
        __syncthreads();
#pragma unroll
        for (int ds = 0; ds < 8; ds++) {
            int d8 = ds * 8;
            uint32_t af[2][4], bf[4][2];
#pragma unroll
            for (int mb = 0; mb < 2; mb++) {
                int base = wm + mb * 16 + lp + 63 - d8 - lq;
                af[mb][0] = us[base];
                af[mb][1] = us[base + 8];
                af[mb][2] = us[base - 4];
                af[mb][3] = us[base + 4];
            }
#pragma unroll
            for (int nb = 0; nb < 4; nb++) {
                bf[nb][0] = Hs[wn + nb * 8 + lp][d8 + lq];
                bf[nb][1] = Hs[wn + nb * 8 + lp][d8 + lq + 4];
            }
#pragma unroll
            for (int mb = 0; mb < 2; mb++)
#pragma unroll
                for (int nb = 0; nb < 4; nb++)
                    mma_tf32(acc[mb][nb], af[mb], bf[nb], acc[mb][nb]);
        }
        __syncthreads();
    }
#pragma unroll
    for (int mb = 0; mb < 2; mb++)
#pragma unroll
        for (int nb = 0; nb < 4; nb++) {
            int t = t0 + wm + mb * 16 + lp;
            int k = k0 + wn + nb * 8 + lq * 2;
            float2 v0 = make_float2(acc[mb][nb][0], acc[mb][nb][1]);
            float2 v1 = make_float2(acc[mb][nb][2], acc[mb][nb][3]);
            *(float2*)&mm[((size_t)b * SEQ + t) * MEM + k] = v0;
            *(float2*)&mm[((size_t)b * SEQ + t + 8) * MEM + k] = v1;
        }
}

// ---------------- kernel 4: h = relu([m|x] @ Wh + b), tf32 tensor cores ----------------
// 32768 x 512, K = 768.  BM=128, BN=128, BK=8, 256 threads (8 warps, 2x4),
// warp tile 64x32, double-buffered smem.
__global__ __launch_bounds__(256) void k_h(const float* __restrict__ mm,
                                           const float* __restrict__ x,
                                           const float* __restrict__ W,
                                           const float* __restrict__ bias,
                                           float* __restrict__ h,
                                           float* __restrict__ hn) {
    __shared__ __align__(16) uint32_t As[2][8][136];
    __shared__ __align__(16) uint32_t Bs[2][8][136];
    int tid = threadIdx.x;
    int lane = tid & 31, wid = tid >> 5;
    int wm = (wid & 1) * 64, wn = (wid >> 1) * 32;
    int lp = lane >> 2, lq = lane & 3;
    int m0 = blockIdx.y * 128, n0 = blockIdx.x * 128;

    int ar = tid >> 1, ak = (tid & 1) * 4;      // A: 128 rows x 8k, 1 float4/thread
    int br = tid >> 5, bn = (tid & 31) * 4;     // B: 8k x 128n, 1 float4/thread
    int arow = m0 + ar;

    float acc[4][4][4] = {};
    float4 va, vb;

    // prologue: tile kt = 0 (k < 256 -> m region)
    va = *(const float4*)(mm + (size_t)arow * MEM + ak);
    vb = *(const float4*)(W + (size_t)br * HID + n0 + bn);
    int buf = 0;
    As[0][ak + 0][ar] = f2tf(va.x); As[0][ak + 1][ar] = f2tf(va.y);
    As[0][ak + 2][ar] = f2tf(va.z); As[0][ak + 3][ar] = f2tf(va.w);
    {
        uint4 t4 = make_uint4(f2tf(vb.x), f2tf(vb.y), f2tf(vb.z), f2tf(vb.w));
        *(uint4*)&Bs[0][br][bn] = t4;
    }
    __syncthreads();

#pragma unroll 1
    for (int kt = 0; kt < MEM + DIN; kt += 8) {
        int nkt = kt + 8;
        if (nkt < MEM + DIN) {
            int k = nkt + ak;
            const float* p = (k < MEM) ? (mm + (size_t)arow * MEM + k)
                                       : (x + (size_t)arow * DIN + (k - MEM));
            va = *(const float4*)p;
            vb = *(const float4*)(W + (size_t)(nkt + br) * HID + n0 + bn);
        }
        // compute on current buffer
        {
            uint32_t af[4][4], bf[4][2];
#pragma unroll
            for (int mb = 0; mb < 4; mb++) {
                int m = wm + mb * 16 + lp;
                af[mb][0] = As[buf][lq][m];
                af[mb][1] = As[buf][lq][m + 8];
                af[mb][2] = As[buf][lq + 4][m];
                af[mb][3] = As[buf][lq + 4][m + 8];
            }
#pragma unroll
            for (int nb = 0; nb < 4; nb++) {
                int n = wn + nb * 8 + lp;
                bf[nb][0] = Bs[buf][lq][n];
                bf[nb][1] = Bs[buf][lq + 4][n];
            }
#pragma unroll
            for (int mb = 0; mb < 4; mb++)
#pragma unroll
                for (int nb = 0; nb < 4; nb++)
                    mma_tf32(acc[mb][nb], af[mb], bf[nb], acc[mb][nb]);
        }
        if (nkt < MEM + DIN) {
            buf ^= 1;
            As[buf][ak + 0][ar] = f2tf(va.x); As[buf][ak + 1][ar] = f2tf(va.y);
            As[buf][ak + 2][ar] = f2tf(va.z); As[buf][ak + 3][ar] = f2tf(va.w);
            uint4 t4 = make_uint4(f2tf(vb.x), f2tf(vb.y), f2tf(vb.z), f2tf(vb.w));
            *(uint4*)&Bs[buf][br][bn] = t4;
            __syncthreads();
        }
    }

    // epilogue: bias + relu + store h (+ h_n for t = SEQ-1 rows)
#pragma unroll
    for (int nb = 0; nb < 4; nb++) {
        int col = n0 + wn + nb * 8 + lq * 2;
        float b0 = bias[col], b1 = bias[col + 1];
#pragma unroll
        for (int mb = 0; mb < 4; mb++) {
            int row0 = m0 + wm + mb * 16 + lp;
            int row1 = row0 + 8;
            float2 v0 = make_float2(fmaxf(acc[mb][nb][0] + b0, 0.f),
                                    fmaxf(acc[mb][nb][1] + b1, 0.f));
            float2 v1 = make_float2(fmaxf(acc[mb][nb][2] + b0, 0.f),
                                    fmaxf(acc[mb][nb][3] + b1, 0.f));
            *(float2*)&h[(size_t)row0 * HID + col] = v0;
            *(float2*)&h[(size_t)row1 * HID + col] = v1;
            if ((row1 & (SEQ - 1)) == SEQ - 1) {
                int bidx = row1 >> 9;
                *(float2*)&hn[(size_t)bidx * HID + col] = v1;
            }
        }
    }
}

// ---------------- launch ----------------
extern "C" void kernel_launch(void* const* d_in, const int* in_sizes, int n_in,
                              void* d_out, int out_size) {
    const float* x    = (const float*)d_in[0];
    const float* Wu_w = (const float*)d_in[1];
    const float* Wu_b = (const float*)d_in[2];
    const float* Wh_w = (const float*)d_in[3];
    const float* Wh_b = (const float*)d_in[4];
    const float* A    = (const float*)d_in[5];
    const float* B    = (const float*)d_in[6];

    float* out = (float*)d_out;
    float* h  = out;
    float* hn = out + (size_t)BATCH * SEQ * HID;

    float *pU, *pH, *pM, *pPbase;
    cudaGetSymbolAddress((void**)&pU, g_u);
    cudaGetSymbolAddress((void**)&pH, g_H);
    cudaGetSymbolAddress((void**)&pM, g_m);
    cudaGetSymbolAddress((void**)&pPbase, g_P);
    float* pP[2] = { pPbase, pPbase + MEM * MEM };

    k_init<<<256, 256>>>(A, B);
    k_u<<<BATCH * SEQ / 8, 256>>>(x, Wu_w, Wu_b, pU);

    // H doubling: 9 fused stages (expansion + P^2 in one launch)
    int cur = 0;
    for (int len = 1; len <= 256; len <<= 1) {
        int doP2 = (len < 256);
        k_stage<<<dim3(8, 8, 2), 256>>>(pP[cur], pH, len, pP[cur ^ 1], doP2);
        if (doP2) cur ^= 1;
    }

    k_conv<<<dim3(MEM / 64, SEQ / 64, BATCH), 128>>>(pU, pM);
    k_h<<<dim3(HID / 128, BATCH * SEQ / 128), 256>>>(pM, x, Wh_w, Wh_b, h, hn);
}

// round 4
// speedup vs baseline: 2.2859x; 1.0050x over previous
#include <cuda_runtime.h>
#include <cuda_bf16.h>
#include <cstdint>

#define BATCH 64
#define SEQ   512
#define DIN   512
#define MEM   256
#define HID   512

// ---------------- scratch ----------------
__device__ float g_u[BATCH * SEQ];
__device__ float g_H[MEM * SEQ];
__device__ float g_P[2][MEM * MEM];
__device__ float g_m[(size_t)BATCH * SEQ * MEM];

// ---------------- helpers ----------------
__device__ __forceinline__ uint32_t f2tf(float x) {
    uint32_t r;
    asm("cvt.rna.tf32.f32 %0, %1;" : "=r"(r) : "f"(x));
    return r;
}
__device__ __forceinline__ void mma_tf32(float* d, const uint32_t* a,
                                         const uint32_t* b, const float* c) {
    asm volatile(
        "mma.sync.aligned.m16n8k8.row.col.f32.tf32.tf32.f32 "
        "{%0,%1,%2,%3}, {%4,%5,%6,%7}, {%8,%9}, {%10,%11,%12,%13};\n"
        : "=f"(d[0]), "=f"(d[1]), "=f"(d[2]), "=f"(d[3])
        : "r"(a[0]), "r"(a[1]), "r"(a[2]), "r"(a[3]),
          "r"(b[0]), "r"(b[1]),
          "f"(c[0]), "f"(c[1]), "f"(c[2]), "f"(c[3]));
}

// ---------------- kernel 0: init ----------------
__global__ void k_init(const float* __restrict__ A, const float* __restrict__ B) {
    int i = blockIdx.x * 256 + threadIdx.x;
    g_P[0][i] = A[i];
    if (i < MEM) g_H[i * SEQ] = B[i];
}

// ---------------- kernel 1: u projection ----------------
__global__ void k_u(const float* __restrict__ x, const float* __restrict__ w,
                    const float* __restrict__ bptr, float* __restrict__ u) {
    __shared__ __align__(16) float ws[DIN];
    int tid = threadIdx.x;
    ws[tid] = w[tid];
    ws[tid + 256] = w[tid + 256];
    __syncthreads();
    int warp = tid >> 5, lane = tid & 31;
    int row = blockIdx.x * 8 + warp;
    const float4* x4 = (const float4*)(x + (size_t)row * DIN);
    const float4* w4 = (const float4*)ws;
    float s = 0.f;
#pragma unroll
    for (int i = lane; i < DIN / 4; i += 32) {
        float4 xv = x4[i];
        float4 wv = w4[i];
        s += xv.x * wv.x + xv.y * wv.y + xv.z * wv.z + xv.w * wv.w;
    }
#pragma unroll
    for (int o = 16; o > 0; o >>= 1) s += __shfl_xor_sync(0xffffffffu, s, o);
    if (lane == 0) u[row] = fmaxf(s + bptr[0], 0.f);
}

// ---------------- kernel 2: fused doubling stage (fp32) ----------------
// z=0: H[:, len:2len] = P @ H[:, 0:len]   (ld 512)
// z=1: Pout = P @ P                        (ld 256, only if doP2)
__global__ void k_stage(const float* __restrict__ P, float* __restrict__ H,
                        int len, float* __restrict__ Pout, int doP2) {
    const float* S;
    float* C;
    int ldS, ldC, N;
    if (blockIdx.z == 0) {
        S = H; ldS = SEQ; C = H + len; ldC = SEQ; N = len;
    } else {
        if (!doP2) return;
        S = P; ldS = MEM; C = Pout; ldC = MEM; N = MEM;
    }
    int c0 = blockIdx.x * 32;
    if (c0 >= N) return;
    __shared__ float Ps[32][33];
    __shared__ float Ss[32][33];
    int tx = threadIdx.x & 15, ty = threadIdx.x >> 4;
    int i0 = blockIdx.y * 32;
    float acc00 = 0, acc01 = 0, acc10 = 0, acc11 = 0;
    for (int k0 = 0; k0 < 256; k0 += 32) {
#pragma unroll
        for (int l = 0; l < 4; l++) {
            int idx = threadIdx.x + l * 256;
            int r = idx >> 5, cc = idx & 31;
            Ps[r][cc] = P[(i0 + r) * 256 + k0 + cc];
            int c = c0 + cc;
            Ss[r][cc] = (c < N) ? S[(size_t)(k0 + r) * ldS + c] : 0.f;
        }
        __syncthreads();
#pragma unroll
        for (int k = 0; k < 32; k++) {
            float a0 = Ps[ty * 2][k], a1 = Ps[ty * 2 + 1][k];
            float b0 = Ss[k][tx * 2], b1 = Ss[k][tx * 2 + 1];
            acc00 += a0 * b0; acc01 += a0 * b1;
            acc10 += a1 * b0; acc11 += a1 * b1;
        }
        __syncthreads();
    }
    int i = i0 + ty * 2, c = c0 + tx * 2;
    if (c < N)     { C[(size_t)i * ldC + c] = acc00; C[(size_t)(i + 1) * ldC + c] = acc10; }
    if (c + 1 < N) { C[(size_t)i * ldC + c + 1] = acc01; C[(size_t)(i + 1) * ldC + c + 1] = acc11; }
}

// ---------------- kernel 3: causal conv, tf32 tensor cores ----------------
// m[b,t,k] = sum_d H[k,d] u[b,t-d].  Per block: 64(t) x 64(k) tile.
// A[t,d] = u[t-d] (row-major Toeplitz from smem), B[d,k] = H[k,d] (col-major frag).
__global__ __launch_bounds__(128) void k_conv(const float* __restrict__ u,
                                              float* __restrict__ mm) {
    __shared__ uint32_t us[128];
    __shared__ uint32_t Hs[64][68];
    int b = blockIdx.z;
    int t0 = blockIdx.y * 64;
    int k0 = blockIdx.x * 64;
    int tid = threadIdx.x;
    int lane = tid & 31, wid = tid >> 5;
    int wm = (wid & 1) * 32, wn = (wid >> 1) * 32;
    int lp = lane >> 2, lq = lane & 3;
    const float* urow = u + b * SEQ;

    float acc[2][4][4] = {};
    int ndc = blockIdx.y + 1;
    for (int dc = 0; dc < ndc; dc++) {
        int d0 = dc * 64;
        {
            int idx = t0 - d0 - 63 + tid;
            us[tid] = f2tf((idx >= 0 && idx < SEQ) ? urow[idx] : 0.f);
        }
        {
            int hr = tid >> 1;
            int hc0 = (tid & 1) * 32;
            const float4* hrow = (const float4*)(g_H + (size_t)(k0 + hr) * SEQ + d0 + hc0);
#pragma unroll
            for (int j = 0; j < 8; j++) {
                float4 v = hrow[j];
                Hs[hr][hc0 + j * 4 + 0] = f2tf(v.x);
                Hs[hr][hc0 + j * 4 + 1] = f2tf(v.y);
                Hs[hr][hc0 + j * 4 + 2] = f2tf(v.z);
                Hs[hr][hc0 + j * 4 + 3] = f2tf(v.w);
            }
        }
        __syncthreads();
#pragma unroll
        for (int ds = 0; ds < 8; ds++) {
            int d8 = ds * 8;
            uint32_t af[2][4], bf[4][2];
#pragma unroll
            for (int mb = 0; mb < 2; mb++) {
                int base = wm + mb * 16 + lp + 63 - d8 - lq;
                af[mb][0] = us[base];
                af[mb][1] = us[base + 8];
                af[mb][2] = us[base - 4];
                af[mb][3] = us[base + 4];
            }
#pragma unroll
            for (int nb = 0; nb < 4; nb++) {
                bf[nb][0] = Hs[wn + nb * 8 + lp][d8 + lq];
                bf[nb][1] = Hs[wn + nb * 8 + lp][d8 + lq + 4];
            }
#pragma unroll
            for (int mb = 0; mb < 2; mb++)
#pragma unroll
                for (int nb = 0; nb < 4; nb++)
                    mma_tf32(acc[mb][nb], af[mb], bf[nb], acc[mb][nb]);
        }
        __syncthreads();
    }
#pragma unroll
    for (int mb = 0; mb < 2; mb++)
#pragma unroll
        for (int nb = 0; nb < 4; nb++) {
            int t = t0 + wm + mb * 16 + lp;
            int k = k0 + wn + nb * 8 + lq * 2;
            float2 v0 = make_float2(acc[mb][nb][0], acc[mb][nb][1]);
            float2 v1 = make_float2(acc[mb][nb][2], acc[mb][nb][3]);
            *(float2*)&mm[((size_t)b * SEQ + t) * MEM + k] = v0;
            *(float2*)&mm[((size_t)b * SEQ + t + 8) * MEM + k] = v1;
        }
}

// ---------------- kernel 4: h = relu([m|x] @ Wh + b), tf32 tensor cores ----------------
// 32768 x 512, K = 768.  BM=128, BN=128, BK=8, 256 threads (8 warps, 2x4),
// warp tile 64x32, double-buffered smem.
__global__ __launch_bounds__(256) void k_h(const float* __restrict__ mm,
                                           const float* __restrict__ x,
                                           const float* __restrict__ W,
                                           const float* __restrict__ bias,
                                           float* __restrict__ h,
                                           float* __restrict__ hn) {
    __shared__ __align__(16) uint32_t As[2][8][136];
    __shared__ __align__(16) uint32_t Bs[2][8][136];
    int tid = threadIdx.x;
    int lane = tid & 31, wid = tid >> 5;
    int wm = (wid & 1) * 64, wn = (wid >> 1) * 32;
    int lp = lane >> 2, lq = lane & 3;
    int m0 = blockIdx.y * 128, n0 = blockIdx.x * 128;

    int ar = tid >> 1, ak = (tid & 1) * 4;      // A: 128 rows x 8k, 1 float4/thread
    int br = tid >> 5, bn = (tid & 31) * 4;     // B: 8k x 128n, 1 float4/thread
    int arow = m0 + ar;

    float acc[4][4][4] = {};
    float4 va, vb;

    // prologue: tile kt = 0 (k < 256 -> m region)
    va = *(const float4*)(mm + (size_t)arow * MEM + ak);
    vb = *(const float4*)(W + (size_t)br * HID + n0 + bn);
    int buf = 0;
    As[0][ak + 0][ar] = f2tf(va.x); As[0][ak + 1][ar] = f2tf(va.y);
    As[0][ak + 2][ar] = f2tf(va.z); As[0][ak + 3][ar] = f2tf(va.w);
    {
        uint4 t4 = make_uint4(f2tf(vb.x), f2tf(vb.y), f2tf(vb.z), f2tf(vb.w));
        *(uint4*)&Bs[0][br][bn] = t4;
    }
    __syncthreads();

#pragma unroll 1
    for (int kt = 0; kt < MEM + DIN; kt += 8) {
        int nkt = kt + 8;
        if (nkt < MEM + DIN) {
            int k = nkt + ak;
            const float* p = (k < MEM) ? (mm + (size_t)arow * MEM + k)
                                       : (x + (size_t)arow * DIN + (k - MEM));
            va = *(const float4*)p;
            vb = *(const float4*)(W + (size_t)(nkt + br) * HID + n0 + bn);
        }
        // compute on current buffer
        {
            uint32_t af[4][4], bf[4][2];
#pragma unroll
            for (int mb = 0; mb < 4; mb++) {
                int m = wm + mb * 16 + lp;
                af[mb][0] = As[buf][lq][m];
                af[mb][1] = As[buf][lq][m + 8];
                af[mb][2] = As[buf][lq + 4][m];
                af[mb][3] = As[buf][lq + 4][m + 8];
            }
#pragma unroll
            for (int nb = 0; nb < 4; nb++) {
                int n = wn + nb * 8 + lp;
                bf[nb][0] = Bs[buf][lq][n];
                bf[nb][1] = Bs[buf][lq + 4][n];
            }
#pragma unroll
            for (int mb = 0; mb < 4; mb++)
#pragma unroll
                for (int nb = 0; nb < 4; nb++)
                    mma_tf32(acc[mb][nb], af[mb], bf[nb], acc[mb][nb]);
        }
        if (nkt < MEM + DIN) {
            buf ^= 1;
            As[buf][ak + 0][ar] = f2tf(va.x); As[buf][ak + 1][ar] = f2tf(va.y);
            As[buf][ak + 2][ar] = f2tf(va.z); As[buf][ak + 3][ar] = f2tf(va.w);
            uint4 t4 = make_uint4(f2tf(vb.x), f2tf(vb.y), f2tf(vb.z), f2tf(vb.w));
            *(uint4*)&Bs[buf][br][bn] = t4;
            __syncthreads();
        }
    }

    // epilogue: bias + relu + store h (+ h_n for t = SEQ-1 rows)
#pragma unroll
    for (int nb = 0; nb < 4; nb++) {
        int col = n0 + wn + nb * 8 + lq * 2;
        float b0 = bias[col], b1 = bias[col + 1];
#pragma unroll
        for (int mb = 0; mb < 4; mb++) {
            int row0 = m0 + wm + mb * 16 + lp;
            int row1 = row0 + 8;
            float2 v0 = make_float2(fmaxf(acc[mb][nb][0] + b0, 0.f),
                                    fmaxf(acc[mb][nb][1] + b1, 0.f));
            float2 v1 = make_float2(fmaxf(acc[mb][nb][2] + b0, 0.f),
                                    fmaxf(acc[mb][nb][3] + b1, 0.f));
            *(float2*)&h[(size_t)row0 * HID + col] = v0;
            *(float2*)&h[(size_t)row1 * HID + col] = v1;
            if ((row1 & (SEQ - 1)) == SEQ - 1) {
                int bidx = row1 >> 9;
                *(float2*)&hn[(size_t)bidx * HID + col] = v1;
            }
        }
    }
}

// ---------------- launch ----------------
extern "C" void kernel_launch(void* const* d_in, const int* in_sizes, int n_in,
                              void* d_out, int out_size) {
    const float* x    = (const float*)d_in[0];
    const float* Wu_w = (const float*)d_in[1];
    const float* Wu_b = (const float*)d_in[2];
    const float* Wh_w = (const float*)d_in[3];
    const float* Wh_b = (const float*)d_in[4];
    const float* A    = (const float*)d_in[5];
    const float* B    = (const float*)d_in[6];

    float* out = (float*)d_out;
    float* h  = out;
    float* hn = out + (size_t)BATCH * SEQ * HID;

    float *pU, *pH, *pM, *pPbase;
    cudaGetSymbolAddress((void**)&pU, g_u);
    cudaGetSymbolAddress((void**)&pH, g_H);
    cudaGetSymbolAddress((void**)&pM, g_m);
    cudaGetSymbolAddress((void**)&pPbase, g_P);
    float* pP[2] = { pPbase, pPbase + MEM * MEM };

    k_init<<<256, 256>>>(A, B);
    k_u<<<BATCH * SEQ / 8, 256>>>(x, Wu_w, Wu_b, pU);

    // H doubling: 9 fused stages (expansion + P^2 in one launch)
    int cur = 0;
    for (int len = 1; len <= 256; len <<= 1) {
        int doP2 = (len < 256);
        k_stage<<<dim3(8, 8, 2), 256>>>(pP[cur], pH, len, pP[cur ^ 1], doP2);
        if (doP2) cur ^= 1;
    }

    k_conv<<<dim3(MEM / 64, SEQ / 64, BATCH), 128>>>(pU, pM);
    k_h<<<dim3(HID / 128, BATCH * SEQ / 128), 256>>>(pM, x, Wh_w, Wh_b, h, hn);
}